// round 9
// baseline (speedup 1.0000x reference)
#include <cuda_runtime.h>
#include <cstdint>
#include <cstddef>

#define D_OUT 64
#define D_IN  256
#define CAP   768        // max neighbors per row (Binom(10000,0.01): 67 sigma margin)
#define MAXW  10240      // max adjacency words staged in smem (40KB)
#define MAXNA 16384

// scratch for proj = anchor @ wt  (allocation-free rule: __device__ global)
__device__ float g_proj[(size_t)MAXNA * D_OUT];

// ---------------------------------------------------------------------------
// proj_kernel: proj[r][c] = sum_k anchor[r][k] * wt[k][c]
// 64 rows/block, 256 threads, 4 rows x 4 cols per thread, k tiled in 4x64.
// s_an padded to 65 floats/row to avoid 2-way bank conflicts.
// ---------------------------------------------------------------------------
__global__ __launch_bounds__(256) void proj_kernel(const float* __restrict__ anchor,
                                                   const float* __restrict__ wt,
                                                   int Na) {
    __shared__ float4 s_wt4[64 * 16];    // [k][colgroup] 16 KB
    __shared__ float  s_an[64 * 65];     // [row][k] padded, 16.25 KB

    const int tid  = threadIdx.x;
    const int row0 = blockIdx.x * 64;
    const int cg   = tid & 15;           // col group (4 cols)
    const int rg   = tid >> 4;           // 0..15 (4 rows each)

    const float4* wt4 = (const float4*)wt;       // [256][16] float4
    const float4* an4 = (const float4*)anchor;   // [Na][64]  float4

    float4 acc[4];
    #pragma unroll
    for (int r = 0; r < 4; r++) acc[r] = make_float4(0.f, 0.f, 0.f, 0.f);

    for (int kt = 0; kt < D_IN / 64; kt++) {
        #pragma unroll
        for (int i = 0; i < 4; i++) {
            int g = tid + i * 256;       // 0..1023: [k 0..63][cg 0..15]
            s_wt4[g] = wt4[(size_t)(kt * 64 + (g >> 4)) * 16 + (g & 15)];
        }
        #pragma unroll
        for (int i = 0; i < 4; i++) {
            int g = tid + i * 256;       // 0..1023: [row 0..63][k4 0..15]
            int rr = g >> 4, k4 = g & 15;
            float4 av = make_float4(0.f, 0.f, 0.f, 0.f);
            if (row0 + rr < Na)
                av = an4[(size_t)(row0 + rr) * (D_IN / 4) + kt * 16 + k4];
            float* d = &s_an[rr * 65 + k4 * 4];
            d[0] = av.x; d[1] = av.y; d[2] = av.z; d[3] = av.w;
        }
        __syncthreads();
        #pragma unroll
        for (int k = 0; k < 64; k++) {
            float4 wv = s_wt4[k * 16 + cg];
            #pragma unroll
            for (int r = 0; r < 4; r++) {
                float a = s_an[(rg * 4 + r) * 65 + k];
                acc[r].x += a * wv.x; acc[r].y += a * wv.y;
                acc[r].z += a * wv.z; acc[r].w += a * wv.w;
            }
        }
        __syncthreads();
    }
    #pragma unroll
    for (int r = 0; r < 4; r++) {
        int row = row0 + rg * 4 + r;
        if (row < Na) ((float4*)g_proj)[(size_t)row * 16 + cg] = acc[r];
    }
}

// ---------------------------------------------------------------------------
// attn_kernel: one block per anchor row.
//  - TMA (cp.async.bulk) stages the full 40KB adjacency word-row into smem:
//    bandwidth decoupled from occupancy/register pressure.
//  - Two-pass warp-ballot compaction from smem (contiguous warp segments,
//    deterministic order, ~6 instr / 32 words).
//  - Then neighbor-only scores, softmax, weighted accumulation.
// adjs is 32-bit words (bool canonicalized): nonzero word == True. Masked
// entries are exactly 0 after softmax (exp underflow), so sparse is exact.
// ---------------------------------------------------------------------------
__global__ __launch_bounds__(256) void attn_kernel(const float* __restrict__ x,
                                                   const float* __restrict__ weight,
                                                   const unsigned int* __restrict__ adjs,
                                                   const int* __restrict__ idxp,
                                                   float* __restrict__ out,
                                                   int N, int Na) {
    __shared__ __align__(16) unsigned s_row[MAXW];   // 40 KB
    __shared__ int    s_idx[CAP];                    // 3 KB
    __shared__ float  s_sc[CAP];                     // 3 KB
    __shared__ __align__(16) float s_proj[D_OUT];    // 256 B
    __shared__ int    s_w[9];
    __shared__ float  s_red[8];
    __shared__ float  s_bcast[2];
    __shared__ float  s_acc[256];
    __shared__ __align__(8) unsigned long long s_mbar;

    const int i    = blockIdx.x;
    const int tid  = threadIdx.x;
    const int lane = tid & 31;
    const int wrp  = tid >> 5;

    const int   idx = *idxp;
    const float wsc = weight[idx];
    const unsigned int* adj = adjs + ((size_t)idx * Na + i) * (size_t)N;

    const bool vec = (N <= MAXW) && ((N & 3) == 0) &&
                     ((((uintptr_t)adj) & 15) == 0);

    const unsigned mb  = (unsigned)__cvta_generic_to_shared(&s_mbar);
    const unsigned dst = (unsigned)__cvta_generic_to_shared(s_row);

    if (vec && tid == 0) {
        asm volatile("mbarrier.init.shared.b64 [%0], %1;" :: "r"(mb), "r"(1u) : "memory");
        asm volatile("fence.proxy.async.shared::cta;" ::: "memory");
    }
    __syncthreads();
    if (vec && tid == 0) {
        unsigned bytes = (unsigned)N * 4u;
        asm volatile("mbarrier.arrive.expect_tx.shared.b64 _, [%0], %1;"
                     :: "r"(mb), "r"(bytes) : "memory");
        asm volatile(
            "cp.async.bulk.shared::cluster.global.mbarrier::complete_tx::bytes "
            "[%0], [%1], %2, [%3];"
            :: "r"(dst), "l"(adj), "r"(bytes), "r"(mb) : "memory");
    }

    // overlap: load this row's projection while TMA streams
    if (tid < 16) {
        float4 pv = ((const float4*)g_proj)[(size_t)i * 16 + tid];
        ((float4*)s_proj)[tid] = pv;
    }

    if (vec) {
        unsigned done = 0;
        while (!done) {
            asm volatile(
                "{\n\t.reg .pred p;\n\t"
                "mbarrier.try_wait.parity.acquire.cta.shared::cta.b64 p, [%1], %2, 0x989680;\n\t"
                "selp.b32 %0, 1, 0, p;\n\t}"
                : "=r"(done) : "r"(mb), "r"(0u) : "memory");
        }
    }
    __syncthreads();

    // ---- contiguous warp segments over the N words ----
    const int seg = (N + 7) >> 3;
    const int ws  = wrp * seg;
    const int we  = min(N, ws + seg);

    // ---- pass 1: per-warp counts via ballot ----
    int c = 0;
    if (vec) {
        #pragma unroll 4
        for (int j0 = ws; j0 < we; j0 += 32) {
            int j = j0 + lane;
            unsigned w = (j < we) ? s_row[j] : 0u;
            c += __popc(__ballot_sync(0xffffffffu, w != 0u));
        }
    } else {
        #pragma unroll 4
        for (int j0 = ws; j0 < we; j0 += 32) {
            int j = j0 + lane;
            unsigned w = (j < we) ? adj[j] : 0u;
            c += __popc(__ballot_sync(0xffffffffu, w != 0u));
        }
    }
    if (lane == 0) s_w[wrp] = c;
    __syncthreads();
    if (tid == 0) {
        int run = 0;
        #pragma unroll
        for (int k2 = 0; k2 < 8; k2++) { int t = s_w[k2]; s_w[k2] = run; run += t; }
        s_w[8] = run;
    }
    __syncthreads();
    const int cnt = min(s_w[8], CAP);

    // ---- pass 2: in-order ballot emit ----
    {
        int wo = s_w[wrp];
        const unsigned lmask = (1u << lane) - 1u;
        if (vec) {
            #pragma unroll 4
            for (int j0 = ws; j0 < we; j0 += 32) {
                int j = j0 + lane;
                unsigned w = (j < we) ? s_row[j] : 0u;
                unsigned mk = __ballot_sync(0xffffffffu, w != 0u);
                if (w) { int p = wo + __popc(mk & lmask); if (p < CAP) s_idx[p] = j; }
                wo += __popc(mk);
            }
        } else {
            #pragma unroll 4
            for (int j0 = ws; j0 < we; j0 += 32) {
                int j = j0 + lane;
                unsigned w = (j < we) ? adj[j] : 0u;
                unsigned mk = __ballot_sync(0xffffffffu, w != 0u);
                if (w) { int p = wo + __popc(mk & lmask); if (p < CAP) s_idx[p] = j; }
                wo += __popc(mk);
            }
        }
    }
    __syncthreads();

    if (cnt > 0) {
        // ---- scores: 16 threads per neighbor, float4 partial dots ----
        const int g = tid >> 4, l16 = tid & 15;
        const unsigned gmask = 0xFFFFu << (lane & 16);
        const float4 pv = ((const float4*)s_proj)[l16];
        for (int n = g; n < cnt; n += 16) {
            const float4* xr = (const float4*)(x + (size_t)s_idx[n] * D_OUT);
            float4 xv = xr[l16];
            float p = xv.x * pv.x + xv.y * pv.y + xv.z * pv.z + xv.w * pv.w;
            p += __shfl_down_sync(gmask, p, 8);
            p += __shfl_down_sync(gmask, p, 4);
            p += __shfl_down_sync(gmask, p, 2);
            p += __shfl_down_sync(gmask, p, 1);
            if (l16 == 0) s_sc[n] = p;
        }
        __syncthreads();

        // ---- softmax over cnt scores ----
        float m = -3.4e38f;
        for (int n = tid; n < cnt; n += 256) m = fmaxf(m, s_sc[n]);
        #pragma unroll
        for (int o = 16; o; o >>= 1) m = fmaxf(m, __shfl_xor_sync(0xffffffffu, m, o));
        if (lane == 0) s_red[wrp] = m;
        __syncthreads();
        if (tid == 0) {
            float mm = s_red[0];
            #pragma unroll
            for (int k2 = 1; k2 < 8; k2++) mm = fmaxf(mm, s_red[k2]);
            s_bcast[0] = mm;
        }
        __syncthreads();
        m = s_bcast[0];

        const float invT = 1.0f / 0.07f;
        float ls = 0.f;
        for (int n = tid; n < cnt; n += 256) {
            float e = __expf((s_sc[n] - m) * invT);
            s_sc[n] = e;
            ls += e;
        }
        #pragma unroll
        for (int o = 16; o; o >>= 1) ls += __shfl_xor_sync(0xffffffffu, ls, o);
        if (lane == 0) s_red[wrp] = ls;
        __syncthreads();
        if (tid == 0) {
            float ss = 0.f;
            #pragma unroll
            for (int k2 = 0; k2 < 8; k2++) ss += s_red[k2];
            s_bcast[1] = ss;
        }
        __syncthreads();
        const float scale = wsc / s_bcast[1];

        // ---- output: out[i][c] = scale * sum_n e_n * x[j_n][c] ----
        const int cc = tid & 63, part = tid >> 6;
        float acc = 0.f;
        for (int n = part; n < cnt; n += 4)
            acc += s_sc[n] * x[(size_t)s_idx[n] * D_OUT + cc];
        s_acc[tid] = acc;
        __syncthreads();
        if (tid < 64)
            out[(size_t)i * D_OUT + tid] =
                scale * (s_acc[tid] + s_acc[tid + 64] + s_acc[tid + 128] + s_acc[tid + 192]);
    } else {
        // empty adjacency row: reference softmax degenerates to uniform 1/N
        const int cc = tid & 63, part = tid >> 6;
        float acc = 0.f;
        for (int j = part; j < N; j += 4) acc += x[(size_t)j * D_OUT + cc];
        s_acc[tid] = acc;
        __syncthreads();
        if (tid < 64)
            out[(size_t)i * D_OUT + tid] =
                wsc * (s_acc[tid] + s_acc[tid + 64] + s_acc[tid + 128] + s_acc[tid + 192]) / (float)N;
    }
}

// ---------------------------------------------------------------------------
extern "C" void kernel_launch(void* const* d_in, const int* in_sizes, int n_in,
                              void* d_out, int out_size) {
    const float*        x      = (const float*)d_in[0];
    const float*        weight = (const float*)d_in[1];
    const unsigned int* adjs   = (const unsigned int*)d_in[2];
    const int*          idxp   = (const int*)d_in[3];
    const float*        anchor = (const float*)d_in[4];
    const float*        wt     = (const float*)d_in[5];
    float*              out    = (float*)d_out;

    const int N  = in_sizes[0] / D_OUT;   // 10000
    const int Na = in_sizes[4] / D_IN;    // 10000

    proj_kernel<<<(Na + 63) / 64, 256>>>(anchor, wt, Na);
    attn_kernel<<<Na, 256>>>(x, weight, adjs, idxp, out, N, Na);
}